// round 8
// baseline (speedup 1.0000x reference)
#include <cuda_runtime.h>
#include <math.h>

#define Nn   12288
#define Ee   393216
#define INF  256
#define Hh   128
#define DZv  64

// ---------------- scratch (static device globals; no allocation) ------------
__device__ __align__(16) int   g_degi[Nn];
__device__ __align__(16) float g_t0[Nn * Hh];      // (features @ W0) * norm   (pre-norm L1)
__device__ __align__(16) float g_hid[Nn * Hh];     // raw aggregation (un-normalized)
__device__ __align__(16) float g_t1[Nn * DZv];     // norm^2 * (hid_agg @ Wm)  (post-L1 + pre-L2 folded)
__device__ __align__(16) float g_t2[Nn * DZv];
__device__ __align__(16) float g_aggM[Nn * DZv];
__device__ __align__(16) float g_aggS[Nn * DZv];
__device__ __align__(16) float g_Z[Nn * DZv];
__device__ __align__(16) int   g_src[Ee];
__device__ __align__(16) int   g_dst[Ee];

__device__ __forceinline__ float node_norm(int node) {
    return rsqrtf(fmaxf((float)g_degi[node], 1.0f));
}

// ---------------- edge index conversion (dtype probed on device) -------------
// Layout (2,E). int64: every odd 32-bit word is a high word = 0 (ids < 2^31).
__global__ void k_cvt_idx(const int* __restrict__ ei) {
    __shared__ int s_is64;
    if (threadIdx.x == 0) {
        int is64 = 1;
        for (int i = 0; i < 32; ++i)
            if (ei[2 * i + 1] != 0) { is64 = 0; break; }
        s_is64 = is64;
    }
    __syncthreads();
    int e = blockIdx.x * blockDim.x + threadIdx.x;
    if (e >= Ee) return;
    if (s_is64) {
        g_src[e] = ei[2 * e];
        g_dst[e] = ei[2 * (Ee + e)];
    } else {
        g_src[e] = ei[e];
        g_dst[e] = ei[Ee + e];
    }
}

// ---------------- zero all accumulators --------------------------------------
__global__ void k_zero() {
    int i = blockIdx.x * blockDim.x + threadIdx.x;
    int stride = gridDim.x * blockDim.x;
    for (int j = i; j < Nn; j += stride) g_degi[j] = 0;
    for (int j = i; j < Nn * Hh; j += stride) g_hid[j] = 0.f;
    for (int j = i; j < Nn * DZv; j += stride) { g_aggM[j] = 0.f; g_aggS[j] = 0.f; }
}

// ---------------- in-degree (exact int atomics) ------------------------------
__global__ void k_degree() {
    int e = blockIdx.x * blockDim.x + threadIdx.x;
    if (e < Ee) atomicAdd(&g_degi[g_dst[e]], 1);
}

// ---------------- t0[r][c] = norm[r] * sum_k f[r][k] W0[k][c]  --------------
__global__ void k_t0(const float* __restrict__ F, const float* __restrict__ W0) {
    int id = blockIdx.x * blockDim.x + threadIdx.x;
    if (id >= Nn * Hh) return;
    int r = id >> 7;           // / Hh
    int c = id & (Hh - 1);
    const float* f = F + (size_t)r * INF;
    float acc = 0.f;
    for (int k = 0; k < INF; ++k)
        acc += f[k] * W0[(size_t)k * Hh + c];
    g_t0[id] = acc * node_norm(r);
}

// ---------------- hid[dst][c] += t0[src][c]  (scalar atomics) ----------------
__global__ void k_scatter_h() {
    long long gtid = (long long)blockIdx.x * blockDim.x + threadIdx.x;
    if (gtid >= (long long)Ee * Hh) return;
    int e = (int)(gtid >> 7);
    int c = (int)(gtid & (Hh - 1));
    atomicAdd(&g_hid[(size_t)g_dst[e] * Hh + c], g_t0[(size_t)g_src[e] * Hh + c]);
}

// ---------------- t1/t2[r][c] = norm[r]^2 * sum_k hid[r][k] W{m,s}[k][c] -----
// (post-norm of layer 1 and pre-norm of layer 2 folded: both are norm[r])
__global__ void k_t12(const float* __restrict__ Wm, const float* __restrict__ Ws) {
    int id = blockIdx.x * blockDim.x + threadIdx.x;
    if (id >= Nn * DZv) return;
    int r = id >> 6;           // / DZv
    int c = id & (DZv - 1);
    const float* h = g_hid + (size_t)r * Hh;
    float a1 = 0.f, a2 = 0.f;
    for (int k = 0; k < Hh; ++k) {
        float hv = h[k];
        a1 += hv * Wm[(size_t)k * DZv + c];
        a2 += hv * Ws[(size_t)k * DZv + c];
    }
    float n = node_norm(r);
    float n2 = n * n;
    g_t1[id] = a1 * n2;
    g_t2[id] = a2 * n2;
}

// ---------------- aggM/aggS[dst][c] += t1/t2[src][c] -------------------------
__global__ void k_scatter_ms() {
    long long gtid = (long long)blockIdx.x * blockDim.x + threadIdx.x;
    if (gtid >= (long long)Ee * DZv) return;
    int e = (int)(gtid >> 6);
    int c = (int)(gtid & (DZv - 1));
    size_t si = (size_t)g_src[e] * DZv + c;
    size_t di = (size_t)g_dst[e] * DZv + c;
    atomicAdd(&g_aggM[di], g_t1[si]);
    atomicAdd(&g_aggS[di], g_t2[si]);
}

// ---------------- Z = noise * exp(relu(aggS*norm)) + relu(aggM*norm) ---------
__global__ void k_z(const float* __restrict__ noise) {
    int i = blockIdx.x * blockDim.x + threadIdx.x;
    if (i >= Nn * DZv) return;
    float n = node_norm(i >> 6);
    float m = fmaxf(g_aggM[i] * n, 0.0f);
    float s = fmaxf(g_aggS[i] * n, 0.0f);
    g_Z[i] = noise[i] * expf(s) + m;
}

// ---------------- out = Z @ Z^T  (N x N, K = 64) ----------------------------
__global__ void k_zzt(float* __restrict__ out) {
    __shared__ float As[64][68];
    __shared__ float Bs[64][68];
    int tid = threadIdx.x;
    int tx = tid & 15, ty = tid >> 4;
    int r0 = blockIdx.y * 64, c0 = blockIdx.x * 64;

    for (int i = tid; i < 64 * 16; i += 256) {
        int row = i >> 4;
        int kq = i & 15;
        float4 a = *(const float4*)&g_Z[(size_t)(r0 + row) * DZv + kq * 4];
        As[kq * 4 + 0][row] = a.x;
        As[kq * 4 + 1][row] = a.y;
        As[kq * 4 + 2][row] = a.z;
        As[kq * 4 + 3][row] = a.w;
        float4 b = *(const float4*)&g_Z[(size_t)(c0 + row) * DZv + kq * 4];
        Bs[kq * 4 + 0][row] = b.x;
        Bs[kq * 4 + 1][row] = b.y;
        Bs[kq * 4 + 2][row] = b.z;
        Bs[kq * 4 + 3][row] = b.w;
    }
    __syncthreads();

    float acc[4][4] = {};
#pragma unroll
    for (int k = 0; k < 64; ++k) {
        float4 a = *(float4*)&As[k][ty * 4];
        float4 b = *(float4*)&Bs[k][tx * 4];
        float av[4] = {a.x, a.y, a.z, a.w};
        float bv[4] = {b.x, b.y, b.z, b.w};
#pragma unroll
        for (int i = 0; i < 4; ++i)
#pragma unroll
            for (int j = 0; j < 4; ++j)
                acc[i][j] += av[i] * bv[j];
    }

#pragma unroll
    for (int i = 0; i < 4; ++i) {
        size_t r = r0 + ty * 4 + i;
        float4 o = make_float4(acc[i][0], acc[i][1], acc[i][2], acc[i][3]);
        *(float4*)&out[r * Nn + c0 + tx * 4] = o;
    }
}

// ---------------- launch ----------------------------------------------------
extern "C" void kernel_launch(void* const* d_in, const int* in_sizes, int n_in,
                              void* d_out, int out_size) {
    const float* features = (const float*)d_in[0];
    const float* W0       = (const float*)d_in[1];
    const float* Wm       = (const float*)d_in[2];
    const float* Ws       = (const float*)d_in[3];
    const float* noise    = (const float*)d_in[4];
    const int*   ei       = (const int*)d_in[5];
    float* out = (float*)d_out;

    k_cvt_idx<<<(Ee + 255) / 256, 256>>>(ei);
    k_zero<<<2048, 256>>>();
    k_degree<<<Ee / 256, 256>>>();

    // t0 = (features @ W0) * norm
    k_t0<<<(Nn * Hh + 255) / 256, 256>>>(features, W0);

    // hid[dst] += t0[src]
    k_scatter_h<<<(int)(((long long)Ee * Hh + 255) / 256), 256>>>();

    // t1 = norm^2*(hid@Wm) ; t2 = norm^2*(hid@Ws)
    k_t12<<<(Nn * DZv + 255) / 256, 256>>>(Wm, Ws);

    // aggM[dst] += t1[src] ; aggS[dst] += t2[src]
    k_scatter_ms<<<(int)(((long long)Ee * DZv + 255) / 256), 256>>>();

    // Z = noise * exp(relu(aggS*norm)) + relu(aggM*norm)
    k_z<<<(Nn * DZv + 255) / 256, 256>>>(noise);

    // adj_logits = Z @ Z^T
    k_zzt<<<dim3(Nn / 64, Nn / 64), 256>>>(out);
}

// round 11
// speedup vs baseline: 1.8697x; 1.8697x over previous
#include <cuda_runtime.h>
#include <cuda_bf16.h>
#include <math.h>

#define Nn   12288
#define Ee   393216
#define INF  256
#define Hh   128
#define DZv  64

// ---------------- scratch (device globals; NEVER passed as kernel args) -----
__device__ __align__(16) int   g_degi[Nn];
__device__ __align__(16) float g_t0[Nn * Hh];
__device__ __align__(16) float g_hid[Nn * Hh];
__device__ __align__(16) float g_t1[Nn * DZv];
__device__ __align__(16) float g_t2[Nn * DZv];
__device__ __align__(16) float g_aggM[Nn * DZv];
__device__ __align__(16) float g_aggS[Nn * DZv];
__device__ __align__(16) __nv_bfloat16 g_Za[Nn * 192];  // [hi | lo | hi]
__device__ __align__(16) __nv_bfloat16 g_Zb[Nn * 192];  // [hi | hi | lo]
__device__ __align__(16) int   g_src[Ee];
__device__ __align__(16) int   g_dst[Ee];

// buffer selectors (resolved ON DEVICE — the whole point)
#define SEL_T0  0
#define SEL_HID 1
#define SEL_T1  2
#define SEL_T2  3
__device__ __forceinline__ float* sel_buf(int s) {
    switch (s) {
        case SEL_T0:  return g_t0;
        case SEL_HID: return g_hid;
        case SEL_T1:  return g_t1;
        default:      return g_t2;
    }
}

__device__ __forceinline__ float node_norm(int node) {
    return rsqrtf(fmaxf((float)g_degi[node], 1.0f));
}

// ---------------- edge index conversion (dtype probed on device) -------------
__global__ void k_cvt_idx(const int* __restrict__ ei) {
    __shared__ int s_is64;
    if (threadIdx.x == 0) {
        int is64 = 1;
        for (int i = 0; i < 32; ++i)
            if (ei[2 * i + 1] != 0) { is64 = 0; break; }
        s_is64 = is64;
    }
    __syncthreads();
    int e = blockIdx.x * blockDim.x + threadIdx.x;
    if (e >= Ee) return;
    if (s_is64) {
        g_src[e] = ei[2 * e];
        g_dst[e] = ei[2 * (Ee + e)];
    } else {
        g_src[e] = ei[e];
        g_dst[e] = ei[Ee + e];
    }
}

// ---------------- zero accumulators ------------------------------------------
__global__ void k_zero() {
    int i = blockIdx.x * blockDim.x + threadIdx.x;
    int stride = gridDim.x * blockDim.x;
    for (int j = i; j < Nn; j += stride) g_degi[j] = 0;
    for (int j = i; j < Nn * Hh; j += stride) g_hid[j] = 0.f;
    for (int j = i; j < Nn * DZv; j += stride) { g_aggM[j] = 0.f; g_aggS[j] = 0.f; }
}

__global__ void k_degree() {
    int e = blockIdx.x * blockDim.x + threadIdx.x;
    if (e < Ee) atomicAdd(&g_degi[g_dst[e]], 1);
}

// ---------------- tiled row-scaled SGEMM: C = (A @ B) * norm[r]^mode ---------
// A: input arg if a_sel<0 else device scratch. B: always a real input pointer.
// C: device scratch via c_sel. BM=64, BN=64, BK=16; 256 threads; 4x4/thread.
__global__ void k_gemm_rowscale(const float* __restrict__ Aarg,
                                const float* __restrict__ B,
                                int a_sel, int c_sel,
                                int K, int Ncols, int mode) {
    const float* A = (a_sel < 0) ? Aarg : sel_buf(a_sel);
    float* C = sel_buf(c_sel);

    __shared__ float As[16][68];
    __shared__ float Bs[16][68];
    int tid = threadIdx.x;
    int tx = tid & 15, ty = tid >> 4;
    int r0 = blockIdx.y * 64, c0 = blockIdx.x * 64;

    float acc[4][4] = {};

    for (int k0 = 0; k0 < K; k0 += 16) {
        {
            int row = tid >> 2;
            int kk  = (tid & 3) * 4;
            float4 v = *(const float4*)&A[(size_t)(r0 + row) * K + k0 + kk];
            As[kk + 0][row] = v.x;
            As[kk + 1][row] = v.y;
            As[kk + 2][row] = v.z;
            As[kk + 3][row] = v.w;
        }
        {
            int krow = tid >> 4;
            int col  = (tid & 15) * 4;
            float4 w = *(const float4*)&B[(size_t)(k0 + krow) * Ncols + c0 + col];
            *(float4*)&Bs[krow][col] = w;
        }
        __syncthreads();

#pragma unroll
        for (int k = 0; k < 16; ++k) {
            float4 a = *(float4*)&As[k][ty * 4];
            float4 b = *(float4*)&Bs[k][tx * 4];
            float av[4] = {a.x, a.y, a.z, a.w};
            float bv[4] = {b.x, b.y, b.z, b.w};
#pragma unroll
            for (int i = 0; i < 4; ++i)
#pragma unroll
                for (int j = 0; j < 4; ++j)
                    acc[i][j] += av[i] * bv[j];
        }
        __syncthreads();
    }

#pragma unroll
    for (int i = 0; i < 4; ++i) {
        int r = r0 + ty * 4 + i;
        float n = node_norm(r);
        float s = (mode == 2) ? n * n : n;
        float4 o = make_float4(acc[i][0] * s, acc[i][1] * s, acc[i][2] * s, acc[i][3] * s);
        *(float4*)&C[(size_t)r * Ncols + c0 + tx * 4] = o;
    }
}

// ---------------- scatter: hid[dst] += t0[src]  (warp/edge, scalar atomics) --
__global__ void k_scatter_h() {
    int gtid = blockIdx.x * blockDim.x + threadIdx.x;
    int e = gtid >> 5;
    int lane = gtid & 31;
    if (e >= Ee) return;
    int s = g_src[e];
    int d = g_dst[e];
    float4 v = ((const float4*)&g_t0[(size_t)s * Hh])[lane];
    float* p = &g_hid[(size_t)d * Hh + lane * 4];
    atomicAdd(p + 0, v.x);
    atomicAdd(p + 1, v.y);
    atomicAdd(p + 2, v.z);
    atomicAdd(p + 3, v.w);
}

// ---------------- scatter mean+logstd (warp/edge, scalar atomics) ------------
__global__ void k_scatter_ms() {
    int gtid = blockIdx.x * blockDim.x + threadIdx.x;
    int e = gtid >> 5;
    int lane = gtid & 31;
    if (e >= Ee) return;
    int s = g_src[e];
    int d = g_dst[e];
    const float* tsrc;
    float* tdst;
    int q;
    if (lane < 16) {
        q = lane;
        tsrc = &g_t1[(size_t)s * DZv];
        tdst = &g_aggM[(size_t)d * DZv];
    } else {
        q = lane - 16;
        tsrc = &g_t2[(size_t)s * DZv];
        tdst = &g_aggS[(size_t)d * DZv];
    }
    float4 v = ((const float4*)tsrc)[q];
    float* p = tdst + q * 4;
    atomicAdd(p + 0, v.x);
    atomicAdd(p + 1, v.y);
    atomicAdd(p + 2, v.z);
    atomicAdd(p + 3, v.w);
}

// ---------------- Z + asymmetric bf16 split ----------------------------------
// Za = [hi | lo | hi], Zb = [hi | hi | lo] => Za.Zb^T = hi.hi + lo.hi + hi.lo
__global__ void k_z(const float* __restrict__ noise) {
    int i = blockIdx.x * blockDim.x + threadIdx.x;
    if (i >= Nn * DZv) return;
    int r = i >> 6;
    int c = i & 63;
    float n = node_norm(r);
    float m = fmaxf(g_aggM[i] * n, 0.0f);
    float s = fmaxf(g_aggS[i] * n, 0.0f);
    float z = noise[i] * expf(s) + m;
    __nv_bfloat16 hi = __float2bfloat16(z);
    __nv_bfloat16 lo = __float2bfloat16(z - __bfloat162float(hi));
    size_t base = (size_t)r * 192;
    g_Za[base + c]       = hi;
    g_Za[base + 64 + c]  = lo;
    g_Za[base + 128 + c] = hi;
    g_Zb[base + c]       = hi;
    g_Zb[base + 64 + c]  = hi;
    g_Zb[base + 128 + c] = lo;
}

// ---------------- out = Za @ Zb^T via mma.sync bf16 (K=192) ------------------
#define ZPAD 8
#define ZLD  (64 + ZPAD)

__device__ __forceinline__ unsigned smem_u32(const void* p) {
    return (unsigned)__cvta_generic_to_shared(p);
}

__global__ void __launch_bounds__(256, 2) k_zzt_mma(float* __restrict__ out) {
    __shared__ __align__(16) __nv_bfloat16 As[128][ZLD];
    __shared__ __align__(16) __nv_bfloat16 Bs[128][ZLD];

    int tid  = threadIdx.x;
    int lane = tid & 31;
    int w    = tid >> 5;
    int wm   = w & 1;
    int wn   = w >> 1;
    int r0 = blockIdx.y * 128;
    int c0 = blockIdx.x * 128;

    float acc[4][4][4];
#pragma unroll
    for (int i = 0; i < 4; ++i)
#pragma unroll
        for (int j = 0; j < 4; ++j)
#pragma unroll
            for (int q = 0; q < 4; ++q) acc[i][j][q] = 0.f;

    for (int kc = 0; kc < 3; ++kc) {
#pragma unroll
        for (int it = 0; it < 4; ++it) {
            int quad = tid + it * 256;
            int row = quad >> 3;
            int q   = quad & 7;
            const uint4* ga = (const uint4*)&g_Za[(size_t)(r0 + row) * 192 + kc * 64];
            *(uint4*)&As[row][q * 8] = ga[q];
            const uint4* gb = (const uint4*)&g_Zb[(size_t)(c0 + row) * 192 + kc * 64];
            *(uint4*)&Bs[row][q * 8] = gb[q];
        }
        __syncthreads();

#pragma unroll
        for (int ks = 0; ks < 4; ++ks) {
            int k0 = ks * 16;
            unsigned a[4][4];
#pragma unroll
            for (int i = 0; i < 4; ++i) {
                int m0 = wm * 64 + i * 16;
                unsigned addr = smem_u32(&As[m0 + (lane & 15)][k0 + (lane >> 4) * 8]);
                asm volatile("ldmatrix.sync.aligned.m8n8.x4.shared.b16 {%0,%1,%2,%3}, [%4];"
                             : "=r"(a[i][0]), "=r"(a[i][1]), "=r"(a[i][2]), "=r"(a[i][3])
                             : "r"(addr));
            }
            unsigned b[4][2];
#pragma unroll
            for (int j = 0; j < 4; ++j) {
                int n0 = wn * 32 + j * 8;
                int l = lane & 15;
                unsigned addr = smem_u32(&Bs[n0 + (l & 7)][k0 + (l >> 3) * 8]);
                asm volatile("ldmatrix.sync.aligned.m8n8.x2.shared.b16 {%0,%1}, [%2];"
                             : "=r"(b[j][0]), "=r"(b[j][1])
                             : "r"(addr));
            }
#pragma unroll
            for (int i = 0; i < 4; ++i)
#pragma unroll
                for (int j = 0; j < 4; ++j) {
                    asm volatile(
                        "mma.sync.aligned.m16n8k16.row.col.f32.bf16.bf16.f32 "
                        "{%0,%1,%2,%3}, {%4,%5,%6,%7}, {%8,%9}, {%0,%1,%2,%3};"
                        : "+f"(acc[i][j][0]), "+f"(acc[i][j][1]),
                          "+f"(acc[i][j][2]), "+f"(acc[i][j][3])
                        : "r"(a[i][0]), "r"(a[i][1]), "r"(a[i][2]), "r"(a[i][3]),
                          "r"(b[j][0]), "r"(b[j][1]));
                }
        }
        __syncthreads();
    }

#pragma unroll
    for (int i = 0; i < 4; ++i) {
#pragma unroll
        for (int j = 0; j < 4; ++j) {
            size_t row0 = r0 + wm * 64 + i * 16 + (lane >> 2);
            size_t col  = c0 + wn * 32 + j * 8 + (lane & 3) * 2;
            *(float2*)&out[row0 * Nn + col]       = make_float2(acc[i][j][0], acc[i][j][1]);
            *(float2*)&out[(row0 + 8) * Nn + col] = make_float2(acc[i][j][2], acc[i][j][3]);
        }
    }
}

// ---------------- launch (only true device pointers cross the boundary) ------
extern "C" void kernel_launch(void* const* d_in, const int* in_sizes, int n_in,
                              void* d_out, int out_size) {
    const float* features = (const float*)d_in[0];
    const float* W0       = (const float*)d_in[1];
    const float* Wm       = (const float*)d_in[2];
    const float* Ws       = (const float*)d_in[3];
    const float* noise    = (const float*)d_in[4];
    const int*   ei       = (const int*)d_in[5];
    float* out = (float*)d_out;

    k_cvt_idx<<<(Ee + 255) / 256, 256>>>(ei);
    k_zero<<<2048, 256>>>();
    k_degree<<<Ee / 256, 256>>>();

    // t0 = (features @ W0) * norm   [12288 x 128], K=256
    k_gemm_rowscale<<<dim3(Hh / 64, Nn / 64), 256>>>(features, W0, -1, SEL_T0, INF, Hh, 1);

    // hid[dst] += t0[src]
    k_scatter_h<<<(Ee * 32) / 256, 256>>>();

    // t1 = norm^2*(hid@Wm) ; t2 = norm^2*(hid@Ws)   [12288 x 64], K=128
    k_gemm_rowscale<<<dim3(DZv / 64, Nn / 64), 256>>>(nullptr, Wm, SEL_HID, SEL_T1, Hh, DZv, 2);
    k_gemm_rowscale<<<dim3(DZv / 64, Nn / 64), 256>>>(nullptr, Ws, SEL_HID, SEL_T2, Hh, DZv, 2);

    // aggM[dst] += t1[src] ; aggS[dst] += t2[src]
    k_scatter_ms<<<(Ee * 32) / 256, 256>>>();

    // Z + asymmetric bf16 split
    k_z<<<(Nn * DZv + 255) / 256, 256>>>(noise);

    // adj_logits = Za @ Zb^T  (== Z @ Z^T up to ~1e-5)
    k_zzt_mma<<<dim3(Nn / 128, Nn / 128), 256>>>(out);
}

// round 12
// speedup vs baseline: 2.6998x; 1.4439x over previous
#include <cuda_runtime.h>
#include <cuda_bf16.h>
#include <math.h>

#define Nn   12288
#define Ee   393216
#define INF  256
#define Hh   128
#define DZv  64

// ---------------- scratch (device globals; NEVER passed as kernel args) -----
__device__ __align__(16) int   g_degi[Nn];
__device__ __align__(16) int   g_off[Nn];      // exclusive CSR offsets
__device__ __align__(16) int   g_pos[Nn];      // fill cursors
__device__ __align__(16) int   g_csr[Ee];      // src ids grouped by dst
__device__ __align__(16) float g_t0[Nn * Hh];
__device__ __align__(16) float g_hid[Nn * Hh];
__device__ __align__(16) float g_t1[Nn * DZv];
__device__ __align__(16) float g_t2[Nn * DZv];
__device__ __align__(16) float g_aggM[Nn * DZv];
__device__ __align__(16) float g_aggS[Nn * DZv];
__device__ __align__(16) __nv_bfloat16 g_Za[Nn * 192];  // [hi | lo | hi]
__device__ __align__(16) __nv_bfloat16 g_Zb[Nn * 192];  // [hi | hi | lo]
__device__ __align__(16) int   g_src[Ee];
__device__ __align__(16) int   g_dst[Ee];

// buffer selectors (resolved ON DEVICE — device symbols never cross host ABI)
#define SEL_T0  0
#define SEL_HID 1
#define SEL_T1  2
#define SEL_T2  3
__device__ __forceinline__ float* sel_buf(int s) {
    switch (s) {
        case SEL_T0:  return g_t0;
        case SEL_HID: return g_hid;
        case SEL_T1:  return g_t1;
        default:      return g_t2;
    }
}

__device__ __forceinline__ float node_norm(int node) {
    return rsqrtf(fmaxf((float)g_degi[node], 1.0f));
}

// ---------------- edge index conversion (dtype probed on device) -------------
__global__ void k_cvt_idx(const int* __restrict__ ei) {
    __shared__ int s_is64;
    if (threadIdx.x == 0) {
        int is64 = 1;
        for (int i = 0; i < 32; ++i)
            if (ei[2 * i + 1] != 0) { is64 = 0; break; }
        s_is64 = is64;
    }
    __syncthreads();
    int e = blockIdx.x * blockDim.x + threadIdx.x;
    if (e >= Ee) return;
    if (s_is64) {
        g_src[e] = ei[2 * e];
        g_dst[e] = ei[2 * (Ee + e)];
    } else {
        g_src[e] = ei[e];
        g_dst[e] = ei[Ee + e];
    }
}

// ---------------- zero (only histogram + cursors now) ------------------------
__global__ void k_zero() {
    int i = blockIdx.x * blockDim.x + threadIdx.x;
    if (i < Nn) { g_degi[i] = 0; g_pos[i] = 0; }
}

__global__ void k_degree() {
    int e = blockIdx.x * blockDim.x + threadIdx.x;
    if (e < Ee) atomicAdd(&g_degi[g_dst[e]], 1);
}

// ---------------- exclusive prefix scan of g_degi -> g_off (1 block, 1024) ---
__global__ void k_scan() {
    const int PER = Nn / 1024;   // 12
    int tid = threadIdx.x;
    int lane = tid & 31, wid = tid >> 5;
    int base = tid * PER;
    int loc[PER];
    int sum = 0;
#pragma unroll
    for (int i = 0; i < PER; ++i) { loc[i] = sum; sum += g_degi[base + i]; }
    int v = sum;
#pragma unroll
    for (int off = 1; off < 32; off <<= 1) {
        int nb = __shfl_up_sync(0xffffffffu, v, off);
        if (lane >= off) v += nb;
    }
    __shared__ int ws[32];
    if (lane == 31) ws[wid] = v;
    __syncthreads();
    if (wid == 0) {
        int w = ws[lane];
#pragma unroll
        for (int off = 1; off < 32; off <<= 1) {
            int nb = __shfl_up_sync(0xffffffffu, w, off);
            if (lane >= off) w += nb;
        }
        ws[lane] = w;
    }
    __syncthreads();
    int warp_excl = (wid > 0) ? ws[wid - 1] : 0;
    int thr_excl = warp_excl + v - sum;
#pragma unroll
    for (int i = 0; i < PER; ++i) g_off[base + i] = thr_excl + loc[i];
}

// ---------------- CSR fill (int atomics on cursors only) ---------------------
__global__ void k_fill() {
    int e = blockIdx.x * blockDim.x + threadIdx.x;
    if (e >= Ee) return;
    int d = g_dst[e];
    int p = g_off[d] + atomicAdd(&g_pos[d], 1);
    g_csr[p] = g_src[e];
}

// ---------------- tiled row-scaled SGEMM: C = (A @ B) * norm[r]^mode ---------
__global__ void k_gemm_rowscale(const float* __restrict__ Aarg,
                                const float* __restrict__ B,
                                int a_sel, int c_sel,
                                int K, int Ncols, int mode) {
    const float* A = (a_sel < 0) ? Aarg : sel_buf(a_sel);
    float* C = sel_buf(c_sel);

    __shared__ float As[16][68];
    __shared__ float Bs[16][68];
    int tid = threadIdx.x;
    int tx = tid & 15, ty = tid >> 4;
    int r0 = blockIdx.y * 64, c0 = blockIdx.x * 64;

    float acc[4][4] = {};

    for (int k0 = 0; k0 < K; k0 += 16) {
        {
            int row = tid >> 2;
            int kk  = (tid & 3) * 4;
            float4 v = *(const float4*)&A[(size_t)(r0 + row) * K + k0 + kk];
            As[kk + 0][row] = v.x;
            As[kk + 1][row] = v.y;
            As[kk + 2][row] = v.z;
            As[kk + 3][row] = v.w;
        }
        {
            int krow = tid >> 4;
            int col  = (tid & 15) * 4;
            float4 w = *(const float4*)&B[(size_t)(k0 + krow) * Ncols + c0 + col];
            *(float4*)&Bs[krow][col] = w;
        }
        __syncthreads();

#pragma unroll
        for (int k = 0; k < 16; ++k) {
            float4 a = *(float4*)&As[k][ty * 4];
            float4 b = *(float4*)&Bs[k][tx * 4];
            float av[4] = {a.x, a.y, a.z, a.w};
            float bv[4] = {b.x, b.y, b.z, b.w};
#pragma unroll
            for (int i = 0; i < 4; ++i)
#pragma unroll
                for (int j = 0; j < 4; ++j)
                    acc[i][j] += av[i] * bv[j];
        }
        __syncthreads();
    }

#pragma unroll
    for (int i = 0; i < 4; ++i) {
        int r = r0 + ty * 4 + i;
        float n = node_norm(r);
        float s = (mode == 2) ? n * n : n;
        float4 o = make_float4(acc[i][0] * s, acc[i][1] * s, acc[i][2] * s, acc[i][3] * s);
        *(float4*)&C[(size_t)r * Ncols + c0 + tx * 4] = o;
    }
}

// ---------------- gather-aggregate hid[d] = sum t0[src in-edges] (warp/node) -
__global__ void k_agg_h() {
    int gtid = blockIdx.x * blockDim.x + threadIdx.x;
    int node = gtid >> 5;
    int lane = gtid & 31;
    if (node >= Nn) return;
    int beg = g_off[node];
    int end = beg + g_degi[node];
    float4 acc = make_float4(0.f, 0.f, 0.f, 0.f);
    for (int i = beg; i < end; ++i) {
        int s = g_csr[i];
        float4 v = ((const float4*)&g_t0[(size_t)s * Hh])[lane];
        acc.x += v.x; acc.y += v.y; acc.z += v.z; acc.w += v.w;
    }
    ((float4*)&g_hid[(size_t)node * Hh])[lane] = acc;
}

// ---------------- gather-aggregate aggM/aggS (warp/node, lanes split) --------
__global__ void k_agg_ms() {
    int gtid = blockIdx.x * blockDim.x + threadIdx.x;
    int node = gtid >> 5;
    int lane = gtid & 31;
    if (node >= Nn) return;
    int beg = g_off[node];
    int end = beg + g_degi[node];
    const float* T = (lane < 16) ? g_t1 : g_t2;
    int q = lane & 15;
    float4 acc = make_float4(0.f, 0.f, 0.f, 0.f);
    for (int i = beg; i < end; ++i) {
        int s = g_csr[i];
        float4 v = ((const float4*)&T[(size_t)s * DZv])[q];
        acc.x += v.x; acc.y += v.y; acc.z += v.z; acc.w += v.w;
    }
    float* AGG = (lane < 16) ? g_aggM : g_aggS;
    ((float4*)&AGG[(size_t)node * DZv])[q] = acc;
}

// ---------------- Z + asymmetric bf16 split ----------------------------------
// Za = [hi | lo | hi], Zb = [hi | hi | lo] => Za.Zb^T = hi.hi + lo.hi + hi.lo
__global__ void k_z(const float* __restrict__ noise) {
    int i = blockIdx.x * blockDim.x + threadIdx.x;
    if (i >= Nn * DZv) return;
    int r = i >> 6;
    int c = i & 63;
    float n = node_norm(r);
    float m = fmaxf(g_aggM[i] * n, 0.0f);
    float s = fmaxf(g_aggS[i] * n, 0.0f);
    float z = noise[i] * expf(s) + m;
    __nv_bfloat16 hi = __float2bfloat16(z);
    __nv_bfloat16 lo = __float2bfloat16(z - __bfloat162float(hi));
    size_t base = (size_t)r * 192;
    g_Za[base + c]       = hi;
    g_Za[base + 64 + c]  = lo;
    g_Za[base + 128 + c] = hi;
    g_Zb[base + c]       = hi;
    g_Zb[base + 64 + c]  = hi;
    g_Zb[base + 128 + c] = lo;
}

// ---------------- out = Za @ Zb^T via mma.sync bf16 (K=192) ------------------
#define ZPAD 8
#define ZLD  (64 + ZPAD)

__device__ __forceinline__ unsigned smem_u32(const void* p) {
    return (unsigned)__cvta_generic_to_shared(p);
}

__global__ void __launch_bounds__(256, 2) k_zzt_mma(float* __restrict__ out) {
    __shared__ __align__(16) __nv_bfloat16 As[128][ZLD];
    __shared__ __align__(16) __nv_bfloat16 Bs[128][ZLD];

    int tid  = threadIdx.x;
    int lane = tid & 31;
    int w    = tid >> 5;
    int wm   = w & 1;
    int wn   = w >> 1;
    int r0 = blockIdx.y * 128;
    int c0 = blockIdx.x * 128;

    float acc[4][4][4];
#pragma unroll
    for (int i = 0; i < 4; ++i)
#pragma unroll
        for (int j = 0; j < 4; ++j)
#pragma unroll
            for (int q = 0; q < 4; ++q) acc[i][j][q] = 0.f;

    for (int kc = 0; kc < 3; ++kc) {
#pragma unroll
        for (int it = 0; it < 4; ++it) {
            int quad = tid + it * 256;
            int row = quad >> 3;
            int q   = quad & 7;
            const uint4* ga = (const uint4*)&g_Za[(size_t)(r0 + row) * 192 + kc * 64];
            *(uint4*)&As[row][q * 8] = ga[q];
            const uint4* gb = (const uint4*)&g_Zb[(size_t)(c0 + row) * 192 + kc * 64];
            *(uint4*)&Bs[row][q * 8] = gb[q];
        }
        __syncthreads();

#pragma unroll
        for (int ks = 0; ks < 4; ++ks) {
            int k0 = ks * 16;
            unsigned a[4][4];
#pragma unroll
            for (int i = 0; i < 4; ++i) {
                int m0 = wm * 64 + i * 16;
                unsigned addr = smem_u32(&As[m0 + (lane & 15)][k0 + (lane >> 4) * 8]);
                asm volatile("ldmatrix.sync.aligned.m8n8.x4.shared.b16 {%0,%1,%2,%3}, [%4];"
                             : "=r"(a[i][0]), "=r"(a[i][1]), "=r"(a[i][2]), "=r"(a[i][3])
                             : "r"(addr));
            }
            unsigned b[4][2];
#pragma unroll
            for (int j = 0; j < 4; ++j) {
                int n0 = wn * 32 + j * 8;
                int l = lane & 15;
                unsigned addr = smem_u32(&Bs[n0 + (l & 7)][k0 + (l >> 3) * 8]);
                asm volatile("ldmatrix.sync.aligned.m8n8.x2.shared.b16 {%0,%1}, [%2];"
                             : "=r"(b[j][0]), "=r"(b[j][1])
                             : "r"(addr));
            }
#pragma unroll
            for (int i = 0; i < 4; ++i)
#pragma unroll
                for (int j = 0; j < 4; ++j) {
                    asm volatile(
                        "mma.sync.aligned.m16n8k16.row.col.f32.bf16.bf16.f32 "
                        "{%0,%1,%2,%3}, {%4,%5,%6,%7}, {%8,%9}, {%0,%1,%2,%3};"
                        : "+f"(acc[i][j][0]), "+f"(acc[i][j][1]),
                          "+f"(acc[i][j][2]), "+f"(acc[i][j][3])
                        : "r"(a[i][0]), "r"(a[i][1]), "r"(a[i][2]), "r"(a[i][3]),
                          "r"(b[j][0]), "r"(b[j][1]));
                }
        }
        __syncthreads();
    }

#pragma unroll
    for (int i = 0; i < 4; ++i) {
#pragma unroll
        for (int j = 0; j < 4; ++j) {
            size_t row0 = r0 + wm * 64 + i * 16 + (lane >> 2);
            size_t col  = c0 + wn * 32 + j * 8 + (lane & 3) * 2;
            *(float2*)&out[row0 * Nn + col]       = make_float2(acc[i][j][0], acc[i][j][1]);
            *(float2*)&out[(row0 + 8) * Nn + col] = make_float2(acc[i][j][2], acc[i][j][3]);
        }
    }
}

// ---------------- launch (only true device pointers cross the boundary) ------
extern "C" void kernel_launch(void* const* d_in, const int* in_sizes, int n_in,
                              void* d_out, int out_size) {
    const float* features = (const float*)d_in[0];
    const float* W0       = (const float*)d_in[1];
    const float* Wm       = (const float*)d_in[2];
    const float* Ws       = (const float*)d_in[3];
    const float* noise    = (const float*)d_in[4];
    const int*   ei       = (const int*)d_in[5];
    float* out = (float*)d_out;

    k_cvt_idx<<<(Ee + 255) / 256, 256>>>(ei);
    k_zero<<<(Nn + 255) / 256, 256>>>();
    k_degree<<<Ee / 256, 256>>>();
    k_scan<<<1, 1024>>>();
    k_fill<<<Ee / 256, 256>>>();

    // t0 = (features @ W0) * norm   [12288 x 128], K=256
    k_gemm_rowscale<<<dim3(Hh / 64, Nn / 64), 256>>>(features, W0, -1, SEL_T0, INF, Hh, 1);

    // hid = gather-sum of t0 over in-edges (no atomics)
    k_agg_h<<<(Nn * 32) / 256, 256>>>();

    // t1 = norm^2*(hid@Wm) ; t2 = norm^2*(hid@Ws)   [12288 x 64], K=128
    k_gemm_rowscale<<<dim3(DZv / 64, Nn / 64), 256>>>(nullptr, Wm, SEL_HID, SEL_T1, Hh, DZv, 2);
    k_gemm_rowscale<<<dim3(DZv / 64, Nn / 64), 256>>>(nullptr, Ws, SEL_HID, SEL_T2, Hh, DZv, 2);

    // aggM / aggS = gather-sum of t1 / t2 (no atomics)
    k_agg_ms<<<(Nn * 32) / 256, 256>>>();

    // Z + asymmetric bf16 split
    k_z<<<(Nn * DZv + 255) / 256, 256>>>(noise);

    // adj_logits = Za @ Zb^T  (== Z @ Z^T up to ~1e-5)
    k_zzt_mma<<<dim3(Nn / 128, Nn / 128), 256>>>(out);
}

// round 13
// speedup vs baseline: 3.3878x; 1.2549x over previous
#include <cuda_runtime.h>
#include <cuda_bf16.h>
#include <math.h>

#define Nn   12288
#define Ee   393216
#define INF  256
#define Hh   128
#define DZv  64
#define NB   (Nn / 128)            // 96 tile-rows
#define NBLK (NB * (NB + 1) / 2)   // 4656 triangular tiles

// ---------------- scratch (device globals; NEVER passed as kernel args) -----
__device__ __align__(16) int   g_degi[Nn];
__device__ __align__(16) int   g_off[Nn];
__device__ __align__(16) int   g_pos[Nn];
__device__ __align__(16) int   g_csr[Ee];
__device__ __align__(16) float g_t0[Nn * Hh];
__device__ __align__(16) float g_hid[Nn * Hh];
__device__ __align__(16) float g_t1[Nn * DZv];
__device__ __align__(16) float g_t2[Nn * DZv];
__device__ __align__(16) float g_aggM[Nn * DZv];
__device__ __align__(16) float g_aggS[Nn * DZv];
__device__ __align__(16) __nv_bfloat16 g_Za[Nn * 192];  // [hi | lo | hi]
__device__ __align__(16) __nv_bfloat16 g_Zb[Nn * 192];  // [hi | hi | lo]
__device__ __align__(16) int   g_src[Ee];
__device__ __align__(16) int   g_dst[Ee];

__device__ __forceinline__ float node_norm(int node) {
    return rsqrtf(fmaxf((float)g_degi[node], 1.0f));
}

// ---------------- edge index conversion (dtype probed on device) -------------
__global__ void k_cvt_idx(const int* __restrict__ ei) {
    __shared__ int s_is64;
    if (threadIdx.x == 0) {
        int is64 = 1;
        for (int i = 0; i < 32; ++i)
            if (ei[2 * i + 1] != 0) { is64 = 0; break; }
        s_is64 = is64;
    }
    __syncthreads();
    int e = blockIdx.x * blockDim.x + threadIdx.x;
    if (e >= Ee) return;
    if (s_is64) {
        g_src[e] = ei[2 * e];
        g_dst[e] = ei[2 * (Ee + e)];
    } else {
        g_src[e] = ei[e];
        g_dst[e] = ei[Ee + e];
    }
}

__global__ void k_zero() {
    int i = blockIdx.x * blockDim.x + threadIdx.x;
    if (i < Nn) { g_degi[i] = 0; g_pos[i] = 0; }
}

__global__ void k_degree() {
    int e = blockIdx.x * blockDim.x + threadIdx.x;
    if (e < Ee) atomicAdd(&g_degi[g_dst[e]], 1);
}

// ---------------- exclusive prefix scan of g_degi -> g_off (1 block, 1024) ---
__global__ void k_scan() {
    const int PER = Nn / 1024;
    int tid = threadIdx.x;
    int lane = tid & 31, wid = tid >> 5;
    int base = tid * PER;
    int loc[PER];
    int sum = 0;
#pragma unroll
    for (int i = 0; i < PER; ++i) { loc[i] = sum; sum += g_degi[base + i]; }
    int v = sum;
#pragma unroll
    for (int off = 1; off < 32; off <<= 1) {
        int nb = __shfl_up_sync(0xffffffffu, v, off);
        if (lane >= off) v += nb;
    }
    __shared__ int ws[32];
    if (lane == 31) ws[wid] = v;
    __syncthreads();
    if (wid == 0) {
        int w = ws[lane];
#pragma unroll
        for (int off = 1; off < 32; off <<= 1) {
            int nb = __shfl_up_sync(0xffffffffu, w, off);
            if (lane >= off) w += nb;
        }
        ws[lane] = w;
    }
    __syncthreads();
    int warp_excl = (wid > 0) ? ws[wid - 1] : 0;
    int thr_excl = warp_excl + v - sum;
#pragma unroll
    for (int i = 0; i < PER; ++i) g_off[base + i] = thr_excl + loc[i];
}

__global__ void k_fill() {
    int e = blockIdx.x * blockDim.x + threadIdx.x;
    if (e >= Ee) return;
    int d = g_dst[e];
    int p = g_off[d] + atomicAdd(&g_pos[d], 1);
    g_csr[p] = g_src[e];
}

// ---------------- t0 = (features @ W0) * norm  [tiled SGEMM] -----------------
__global__ void k_gemm_t0(const float* __restrict__ A, const float* __restrict__ B) {
    __shared__ float As[16][68];
    __shared__ float Bs[16][68];
    int tid = threadIdx.x;
    int tx = tid & 15, ty = tid >> 4;
    int r0 = blockIdx.y * 64, c0 = blockIdx.x * 64;

    float acc[4][4] = {};
    for (int k0 = 0; k0 < INF; k0 += 16) {
        {
            int row = tid >> 2;
            int kk  = (tid & 3) * 4;
            float4 v = *(const float4*)&A[(size_t)(r0 + row) * INF + k0 + kk];
            As[kk + 0][row] = v.x; As[kk + 1][row] = v.y;
            As[kk + 2][row] = v.z; As[kk + 3][row] = v.w;
        }
        {
            int krow = tid >> 4;
            int col  = (tid & 15) * 4;
            float4 w = *(const float4*)&B[(size_t)(k0 + krow) * Hh + c0 + col];
            *(float4*)&Bs[krow][col] = w;
        }
        __syncthreads();
#pragma unroll
        for (int k = 0; k < 16; ++k) {
            float4 a = *(float4*)&As[k][ty * 4];
            float4 b = *(float4*)&Bs[k][tx * 4];
            float av[4] = {a.x, a.y, a.z, a.w};
            float bv[4] = {b.x, b.y, b.z, b.w};
#pragma unroll
            for (int i = 0; i < 4; ++i)
#pragma unroll
                for (int j = 0; j < 4; ++j)
                    acc[i][j] += av[i] * bv[j];
        }
        __syncthreads();
    }
#pragma unroll
    for (int i = 0; i < 4; ++i) {
        int r = r0 + ty * 4 + i;
        float n = node_norm(r);
        float4 o = make_float4(acc[i][0] * n, acc[i][1] * n, acc[i][2] * n, acc[i][3] * n);
        *(float4*)&g_t0[(size_t)r * Hh + c0 + tx * 4] = o;
    }
}

// ---------------- merged t1/t2 = norm^2 * (hid @ {Wm,Ws})  -------------------
// one 64-row block computes both outputs; A staged once. Ncols = 64 (1 tile).
__global__ void k_gemm_ms(const float* __restrict__ B1, const float* __restrict__ B2) {
    __shared__ float As[16][68];
    __shared__ float Bs1[16][68];
    __shared__ float Bs2[16][68];
    int tid = threadIdx.x;
    int tx = tid & 15, ty = tid >> 4;
    int r0 = blockIdx.x * 64;

    float acc1[4][4] = {};
    float acc2[4][4] = {};
    for (int k0 = 0; k0 < Hh; k0 += 16) {
        {
            int row = tid >> 2;
            int kk  = (tid & 3) * 4;
            float4 v = *(const float4*)&g_hid[(size_t)(r0 + row) * Hh + k0 + kk];
            As[kk + 0][row] = v.x; As[kk + 1][row] = v.y;
            As[kk + 2][row] = v.z; As[kk + 3][row] = v.w;
        }
        {
            int krow = tid >> 4;
            int col  = (tid & 15) * 4;
            float4 w1 = *(const float4*)&B1[(size_t)(k0 + krow) * DZv + col];
            *(float4*)&Bs1[krow][col] = w1;
            float4 w2 = *(const float4*)&B2[(size_t)(k0 + krow) * DZv + col];
            *(float4*)&Bs2[krow][col] = w2;
        }
        __syncthreads();
#pragma unroll
        for (int k = 0; k < 16; ++k) {
            float4 a = *(float4*)&As[k][ty * 4];
            float av[4] = {a.x, a.y, a.z, a.w};
            float4 b1 = *(float4*)&Bs1[k][tx * 4];
            float bv1[4] = {b1.x, b1.y, b1.z, b1.w};
            float4 b2 = *(float4*)&Bs2[k][tx * 4];
            float bv2[4] = {b2.x, b2.y, b2.z, b2.w};
#pragma unroll
            for (int i = 0; i < 4; ++i)
#pragma unroll
                for (int j = 0; j < 4; ++j) {
                    acc1[i][j] += av[i] * bv1[j];
                    acc2[i][j] += av[i] * bv2[j];
                }
        }
        __syncthreads();
    }
#pragma unroll
    for (int i = 0; i < 4; ++i) {
        int r = r0 + ty * 4 + i;
        float n = node_norm(r);
        float s = n * n;
        float4 o1 = make_float4(acc1[i][0] * s, acc1[i][1] * s, acc1[i][2] * s, acc1[i][3] * s);
        *(float4*)&g_t1[(size_t)r * DZv + tx * 4] = o1;
        float4 o2 = make_float4(acc2[i][0] * s, acc2[i][1] * s, acc2[i][2] * s, acc2[i][3] * s);
        *(float4*)&g_t2[(size_t)r * DZv + tx * 4] = o2;
    }
}

// ---------------- gather-aggregate hid (warp/node) ---------------------------
__global__ void k_agg_h() {
    int gtid = blockIdx.x * blockDim.x + threadIdx.x;
    int node = gtid >> 5;
    int lane = gtid & 31;
    if (node >= Nn) return;
    int beg = g_off[node];
    int end = beg + g_degi[node];
    float4 acc = make_float4(0.f, 0.f, 0.f, 0.f);
    for (int i = beg; i < end; ++i) {
        int s = g_csr[i];
        float4 v = ((const float4*)&g_t0[(size_t)s * Hh])[lane];
        acc.x += v.x; acc.y += v.y; acc.z += v.z; acc.w += v.w;
    }
    ((float4*)&g_hid[(size_t)node * Hh])[lane] = acc;
}

// ---------------- gather-aggregate aggM/aggS (warp/node, lanes split) --------
__global__ void k_agg_ms() {
    int gtid = blockIdx.x * blockDim.x + threadIdx.x;
    int node = gtid >> 5;
    int lane = gtid & 31;
    if (node >= Nn) return;
    int beg = g_off[node];
    int end = beg + g_degi[node];
    const float* T = (lane < 16) ? g_t1 : g_t2;
    int q = lane & 15;
    float4 acc = make_float4(0.f, 0.f, 0.f, 0.f);
    for (int i = beg; i < end; ++i) {
        int s = g_csr[i];
        float4 v = ((const float4*)&T[(size_t)s * DZv])[q];
        acc.x += v.x; acc.y += v.y; acc.z += v.z; acc.w += v.w;
    }
    float* AGG = (lane < 16) ? g_aggM : g_aggS;
    ((float4*)&AGG[(size_t)node * DZv])[q] = acc;
}

// ---------------- Z + asymmetric bf16 split ----------------------------------
__global__ void k_z(const float* __restrict__ noise) {
    int i = blockIdx.x * blockDim.x + threadIdx.x;
    if (i >= Nn * DZv) return;
    int r = i >> 6;
    int c = i & 63;
    float n = node_norm(r);
    float m = fmaxf(g_aggM[i] * n, 0.0f);
    float s = fmaxf(g_aggS[i] * n, 0.0f);
    float z = noise[i] * expf(s) + m;
    __nv_bfloat16 hi = __float2bfloat16(z);
    __nv_bfloat16 lo = __float2bfloat16(z - __bfloat162float(hi));
    size_t base = (size_t)r * 192;
    g_Za[base + c]       = hi;
    g_Za[base + 64 + c]  = lo;
    g_Za[base + 128 + c] = hi;
    g_Zb[base + c]       = hi;
    g_Zb[base + 64 + c]  = hi;
    g_Zb[base + 128 + c] = lo;
}

// ---------------- symmetric ZZ^T: triangular tiles + smem transpose ----------
#define ZPAD 8
#define ZLD  (64 + ZPAD)

union ZSmem {
    struct { __nv_bfloat16 A[128][ZLD]; __nv_bfloat16 B[128][ZLD]; } ab;
    float tr[128][33];
};

__device__ __forceinline__ unsigned smem_u32(const void* p) {
    return (unsigned)__cvta_generic_to_shared(p);
}

__global__ void __launch_bounds__(256, 2) k_zzt_sym(float* __restrict__ out) {
    __shared__ __align__(16) ZSmem sm;

    int tid  = threadIdx.x;
    int lane = tid & 31;
    int w    = tid >> 5;
    int wm   = w & 1;
    int wn   = w >> 1;

    // triangular decode: block b -> (by, bx), bx <= by
    int b = blockIdx.x;
    int by = (int)((sqrtf(8.0f * (float)b + 1.0f) - 1.0f) * 0.5f);
    while ((by + 1) * (by + 2) / 2 <= b) ++by;
    while (by * (by + 1) / 2 > b) --by;
    int bx = b - by * (by + 1) / 2;
    int r0 = by * 128;
    int c0 = bx * 128;

    float acc[4][4][4];
#pragma unroll
    for (int i = 0; i < 4; ++i)
#pragma unroll
        for (int j = 0; j < 4; ++j)
#pragma unroll
            for (int q = 0; q < 4; ++q) acc[i][j][q] = 0.f;

    for (int kc = 0; kc < 3; ++kc) {
#pragma unroll
        for (int it = 0; it < 4; ++it) {
            int quad = tid + it * 256;
            int row = quad >> 3;
            int q   = quad & 7;
            const uint4* ga = (const uint4*)&g_Za[(size_t)(r0 + row) * 192 + kc * 64];
            *(uint4*)&sm.ab.A[row][q * 8] = ga[q];
            const uint4* gb = (const uint4*)&g_Zb[(size_t)(c0 + row) * 192 + kc * 64];
            *(uint4*)&sm.ab.B[row][q * 8] = gb[q];
        }
        __syncthreads();

#pragma unroll
        for (int ks = 0; ks < 4; ++ks) {
            int k0 = ks * 16;
            unsigned a[4][4];
#pragma unroll
            for (int i = 0; i < 4; ++i) {
                int m0 = wm * 64 + i * 16;
                unsigned addr = smem_u32(&sm.ab.A[m0 + (lane & 15)][k0 + (lane >> 4) * 8]);
                asm volatile("ldmatrix.sync.aligned.m8n8.x4.shared.b16 {%0,%1,%2,%3}, [%4];"
                             : "=r"(a[i][0]), "=r"(a[i][1]), "=r"(a[i][2]), "=r"(a[i][3])
                             : "r"(addr));
            }
            unsigned bb[4][2];
#pragma unroll
            for (int j = 0; j < 4; ++j) {
                int n0 = wn * 32 + j * 8;
                int l = lane & 15;
                unsigned addr = smem_u32(&sm.ab.B[n0 + (l & 7)][k0 + (l >> 3) * 8]);
                asm volatile("ldmatrix.sync.aligned.m8n8.x2.shared.b16 {%0,%1}, [%2];"
                             : "=r"(bb[j][0]), "=r"(bb[j][1])
                             : "r"(addr));
            }
#pragma unroll
            for (int i = 0; i < 4; ++i)
#pragma unroll
                for (int j = 0; j < 4; ++j) {
                    asm volatile(
                        "mma.sync.aligned.m16n8k16.row.col.f32.bf16.bf16.f32 "
                        "{%0,%1,%2,%3}, {%4,%5,%6,%7}, {%8,%9}, {%0,%1,%2,%3};"
                        : "+f"(acc[i][j][0]), "+f"(acc[i][j][1]),
                          "+f"(acc[i][j][2]), "+f"(acc[i][j][3])
                        : "r"(a[i][0]), "r"(a[i][1]), "r"(a[i][2]), "r"(a[i][3]),
                          "r"(bb[j][0]), "r"(bb[j][1]));
                }
        }
        __syncthreads();
    }

    // direct store [r, c]
#pragma unroll
    for (int i = 0; i < 4; ++i) {
#pragma unroll
        for (int j = 0; j < 4; ++j) {
            size_t row0 = r0 + wm * 64 + i * 16 + (lane >> 2);
            size_t col  = c0 + wn * 32 + j * 8 + (lane & 3) * 2;
            *(float2*)&out[row0 * Nn + col]       = make_float2(acc[i][j][0], acc[i][j][1]);
            *(float2*)&out[(row0 + 8) * Nn + col] = make_float2(acc[i][j][2], acc[i][j][3]);
        }
    }

    // mirrored store [c, r] via smem transpose (skip diagonal)
    if (bx == by) return;

    for (int chunk = 0; chunk < 4; ++chunk) {
        __syncthreads();
        if (wn == chunk) {
            int rbase = wm * 64 + (lane >> 2);
            int cbase = (lane & 3) * 2;
#pragma unroll
            for (int i = 0; i < 4; ++i)
#pragma unroll
                for (int j = 0; j < 4; ++j) {
                    int r = rbase + i * 16;
                    int c = cbase + j * 8;
                    sm.tr[r][c]         = acc[i][j][0];
                    sm.tr[r][c + 1]     = acc[i][j][1];
                    sm.tr[r + 8][c]     = acc[i][j][2];
                    sm.tr[r + 8][c + 1] = acc[i][j][3];
                }
        }
        __syncthreads();
        int cc0 = tid >> 7;          // 0..1
        int rr  = tid & 127;
#pragma unroll
        for (int it = 0; it < 16; ++it) {
            int cc = cc0 + it * 2;
            out[(size_t)(c0 + chunk * 32 + cc) * Nn + r0 + rr] = sm.tr[rr][cc];
        }
    }
}

// ---------------- launch (only true device pointers cross the boundary) ------
extern "C" void kernel_launch(void* const* d_in, const int* in_sizes, int n_in,
                              void* d_out, int out_size) {
    const float* features = (const float*)d_in[0];
    const float* W0       = (const float*)d_in[1];
    const float* Wm       = (const float*)d_in[2];
    const float* Ws       = (const float*)d_in[3];
    const float* noise    = (const float*)d_in[4];
    const int*   ei       = (const int*)d_in[5];
    float* out = (float*)d_out;

    k_cvt_idx<<<(Ee + 255) / 256, 256>>>(ei);
    k_zero<<<(Nn + 255) / 256, 256>>>();
    k_degree<<<Ee / 256, 256>>>();
    k_scan<<<1, 1024>>>();
    k_fill<<<Ee / 256, 256>>>();

    // t0 = (features @ W0) * norm
    k_gemm_t0<<<dim3(Hh / 64, Nn / 64), 256>>>(features, W0);

    // hid = gather-sum of t0 over in-edges
    k_agg_h<<<(Nn * 32) / 256, 256>>>();

    // t1, t2 = norm^2 * (hid @ {Wm, Ws})  (merged)
    k_gemm_ms<<<Nn / 64, 256>>>(Wm, Ws);

    // aggM / aggS = gather-sum of t1 / t2
    k_agg_ms<<<(Nn * 32) / 256, 256>>>();

    // Z + asymmetric bf16 split
    k_z<<<(Nn * DZv + 255) / 256, 256>>>(noise);

    // adj_logits = Z @ Z^T  (symmetric: triangular tiles + mirrored store)
    k_zzt_sym<<<NBLK, 256>>>(out);
}